// round 5
// baseline (speedup 1.0000x reference)
#include <cuda_runtime.h>
#include <cstdint>
#include <cstddef>

#define B_ 4
#define T_ 8192
#define DIM_ 512
#define H_ 8
#define D_ 64
#define C_ 64
#define N_ 128
#define BH_ 32
#define EPSV 1.1920929e-07f
#define MAX_LR 0.01f

// ---------------- scratch (static device globals; no allocations) ----------------
__device__ float g_s  [(size_t)B_*T_*DIM_];     // rmsnorm(seq)
__device__ float g_kv [(size_t)B_*T_*2*DIM_];   // [k | v]
__device__ float g_q  [(size_t)B_*T_*DIM_];     // s @ Wq
__device__ float g_g1 [(size_t)BH_*N_*D_*D_];   // -grad w1 -> W1eff after scan
__device__ float g_g2 [(size_t)BH_*N_*D_*D_];   // -grad w2 -> W2eff after scan
__device__ float g_vals[(size_t)B_*T_*DIM_];    // merged per-head values (shifted)
__device__ float g_lr  [(size_t)B_*T_*H_];
__device__ float g_gate[(size_t)B_*T_*H_];
__device__ float g_mom [(size_t)B_*N_*H_];
__device__ float g_dec [(size_t)B_*N_*H_];

__device__ __forceinline__ float sigmoidf_(float x) { return 1.f / (1.f + expf(-x)); }

// ---------------- K1: rmsnorm over dim=512 ----------------
__global__ __launch_bounds__(256) void rmsnorm_kernel(const float* __restrict__ seq) {
    size_t row = blockIdx.x;
    const float* in = seq + row * DIM_;
    float* out = g_s + row * DIM_;
    int tid = threadIdx.x;
    float v0 = in[tid], v1 = in[tid + 256];
    float ss = v0 * v0 + v1 * v1;
#pragma unroll
    for (int o = 16; o; o >>= 1) ss += __shfl_xor_sync(0xffffffffu, ss, o);
    __shared__ float wsum[8];
    if ((tid & 31) == 0) wsum[tid >> 5] = ss;
    __syncthreads();
    float tot = 0.f;
#pragma unroll
    for (int w = 0; w < 8; w++) tot += wsum[w];
    float sc = rsqrtf(tot * (1.f / DIM_) + EPSV);
    out[tid] = v0 * sc;
    out[tid + 256] = v1 * sc;
}

// ---------------- K2: per-token lr/gate projections + per-chunk mom/decay ----------------
__global__ __launch_bounds__(256) void proj_kernel(const float* __restrict__ Wstep,
                                                   const float* __restrict__ Wgate,
                                                   const float* __restrict__ Wmom,
                                                   const float* __restrict__ Wdecay) {
    int blk = blockIdx.x;              // b*N_ + nn
    int b = blk >> 7, nn = blk & 127;
    size_t tb = (size_t)b * T_ + (size_t)nn * C_;
    int tid = threadIdx.x, lane = tid & 31, w = tid >> 5;

    // Phase A: per-token 16 dot products (8 step + 8 gate)
    for (int tk = w; tk < C_; tk += 8) {
        const float* srow = g_s + (tb + tk) * DIM_;
        float acc[16];
#pragma unroll
        for (int q = 0; q < 16; q++) acc[q] = 0.f;
        for (int p = lane; p < DIM_; p += 32) {
            float sv = srow[p];
            const float* ws = Wstep + p * H_;
            const float* wg = Wgate + p * H_;
#pragma unroll
            for (int hh = 0; hh < 8; hh++) {
                acc[hh]     += sv * ws[hh];
                acc[8 + hh] += sv * wg[hh];
            }
        }
#pragma unroll
        for (int q = 0; q < 16; q++)
#pragma unroll
            for (int o = 16; o; o >>= 1) acc[q] += __shfl_xor_sync(0xffffffffu, acc[q], o);
        if (lane == 0) {
#pragma unroll
            for (int hh = 0; hh < 8; hh++) {
                g_lr  [(tb + tk) * H_ + hh] = sigmoidf_(acc[hh]) * MAX_LR;
                g_gate[(tb + tk) * H_ + hh] = sigmoidf_(acc[8 + hh]);
            }
        }
    }

    // Phase B: chunk mean then mom/decay gates
    __shared__ float ssum[DIM_];
    for (int p = tid; p < DIM_; p += 256) {
        float a = 0.f;
        for (int tk = 0; tk < C_; tk++) a += g_s[(tb + tk) * DIM_ + p];
        ssum[p] = a * (1.f / C_);
    }
    __syncthreads();
    if (w < 8) {
        float am = 0.f, ad = 0.f;
        for (int p = lane; p < DIM_; p += 32) {
            am += ssum[p] * Wmom[p * H_ + w];
            ad += ssum[p] * Wdecay[p * H_ + w];
        }
#pragma unroll
        for (int o = 16; o; o >>= 1) {
            am += __shfl_xor_sync(0xffffffffu, am, o);
            ad += __shfl_xor_sync(0xffffffffu, ad, o);
        }
        if (lane == 0) {
            g_mom[((size_t)b * N_ + nn) * H_ + w] = sigmoidf_(am);
            g_dec[((size_t)b * N_ + nn) * H_ + w] = sigmoidf_(ad);
        }
    }
}

// ---------------- SGEMM: C[MxN] = A[MxK] @ B[KxN], row-major, 128x128x8 tiles ----------------
__global__ __launch_bounds__(256) void sgemm128(const float* __restrict__ A,
                                                const float* __restrict__ B,
                                                float* __restrict__ C,
                                                int M, int N, int K) {
    __shared__ float As[8][128];
    __shared__ float Bs[8][128];
    int tid = threadIdx.x;
    int brow = blockIdx.y * 128;
    int bcol = blockIdx.x * 128;
    int arow = tid >> 1, acol = (tid & 1) << 2;
    int brw = tid >> 5, bcl = (tid & 31) << 2;
    int ty = (tid >> 4) << 3;
    int tx = (tid & 15) << 3;
    float acc[8][8];
#pragma unroll
    for (int i = 0; i < 8; i++)
#pragma unroll
        for (int j = 0; j < 8; j++) acc[i][j] = 0.f;

    for (int k0 = 0; k0 < K; k0 += 8) {
        float4 av = *(const float4*)(A + (size_t)(brow + arow) * K + k0 + acol);
        As[acol + 0][arow] = av.x;
        As[acol + 1][arow] = av.y;
        As[acol + 2][arow] = av.z;
        As[acol + 3][arow] = av.w;
        *(float4*)&Bs[brw][bcl] = *(const float4*)(B + (size_t)(k0 + brw) * N + bcol + bcl);
        __syncthreads();
#pragma unroll
        for (int kk = 0; kk < 8; kk++) {
            float4 a0 = *(const float4*)&As[kk][ty];
            float4 a1 = *(const float4*)&As[kk][ty + 4];
            float4 b0 = *(const float4*)&Bs[kk][tx];
            float4 b1 = *(const float4*)&Bs[kk][tx + 4];
            float ra[8] = {a0.x, a0.y, a0.z, a0.w, a1.x, a1.y, a1.z, a1.w};
            float rb[8] = {b0.x, b0.y, b0.z, b0.w, b1.x, b1.y, b1.z, b1.w};
#pragma unroll
            for (int i = 0; i < 8; i++)
#pragma unroll
                for (int j = 0; j < 8; j++) acc[i][j] += ra[i] * rb[j];
        }
        __syncthreads();
    }
#pragma unroll
    for (int i = 0; i < 8; i++) {
        float* crow = C + (size_t)(brow + ty + i) * N + bcol + tx;
        float4 o0 = {acc[i][0], acc[i][1], acc[i][2], acc[i][3]};
        float4 o1 = {acc[i][4], acc[i][5], acc[i][6], acc[i][7]};
        *(float4*)crow = o0;
        *(float4*)(crow + 4) = o1;
    }
}

// ---------------- shared-memory 64x64x64 matmul helper (padded ld=65) ----------------
template <bool TA, bool TB>
__device__ __forceinline__ void mm64(const float* A, const float* B, float acc[4][4],
                                     int r0, int c0) {
#pragma unroll 4
    for (int k = 0; k < 64; k++) {
        float a[4], bv[4];
#pragma unroll
        for (int i = 0; i < 4; i++) a[i] = TA ? A[k * 65 + r0 + i] : A[(r0 + i) * 65 + k];
#pragma unroll
        for (int j = 0; j < 4; j++) bv[j] = TB ? B[(c0 + j) * 65 + k] : B[k * 65 + c0 + j];
#pragma unroll
        for (int i = 0; i < 4; i++)
#pragma unroll
            for (int j = 0; j < 4; j++) acc[i][j] += a[i] * bv[j];
    }
}

#define ZERO_ACC(acc)                         \
    _Pragma("unroll") for (int i = 0; i < 4; i++) \
    _Pragma("unroll") for (int j = 0; j < 4; j++) acc[i][j] = 0.f;

// ---------------- K4: per-chunk MLP gradients (surprises = -grad) ----------------
__global__ __launch_bounds__(256) void chunk_grad_kernel(const float* __restrict__ w1,
                                                         const float* __restrict__ w2) {
    int id = blockIdx.x;               // bh*N_ + nn
    int bh = id >> 7, nn = id & 127;
    int b = bh >> 3, h = bh & 7;
    size_t tb = (size_t)b * T_ + (size_t)nn * C_;
    extern __shared__ float sm[];
    float* KC = sm;               // kc [64][65]
    float* G2 = KC + 64 * 65;     // w1 first, then G2
    float* W2 = G2 + 64 * 65;
    float* X1 = W2 + 64 * 65;
    float* HH = X1 + 64 * 65;     // h, then dx1
    __shared__ float lrs[64];
    int tid = threadIdx.x;
    if (tid < 64) lrs[tid] = g_lr[(tb + tid) * H_ + h];
    for (int idx = tid; idx < 4096; idx += 256) {
        int i = idx >> 6, j = idx & 63;
        KC[i * 65 + j] = g_kv[(tb + i) * (2 * DIM_) + h * 64 + j];
        G2[i * 65 + j] = w1[idx];
        W2[i * 65 + j] = w2[idx];
    }
    __syncthreads();
    int r0 = (tid >> 4) << 2;
    int c0 = (tid & 15) << 2;
    float acc[4][4];

    // x1 = kc @ w1 ; h = silu(x1)
    ZERO_ACC(acc);
    mm64<false, false>(KC, G2, acc, r0, c0);
#pragma unroll
    for (int i = 0; i < 4; i++)
#pragma unroll
        for (int j = 0; j < 4; j++) {
            float x = acc[i][j];
            X1[(r0 + i) * 65 + c0 + j] = x;
            HH[(r0 + i) * 65 + c0 + j] = x * sigmoidf_(x);
        }
    __syncthreads();

    // x2 = h @ w2 ; G2 = (2 lr_i / d)(x2 - v)
    ZERO_ACC(acc);
    mm64<false, false>(HH, W2, acc, r0, c0);
#pragma unroll
    for (int i = 0; i < 4; i++)
#pragma unroll
        for (int j = 0; j < 4; j++) {
            int row = r0 + i, col = c0 + j;
            float vc = g_kv[(tb + row) * (2 * DIM_) + DIM_ + h * 64 + col];
            G2[row * 65 + col] = (2.f / 64.f) * lrs[row] * (acc[i][j] - vc);
        }
    __syncthreads();

    // g2 = h^T @ G2  (store -g2)
    ZERO_ACC(acc);
    mm64<true, false>(HH, G2, acc, r0, c0);
    size_t gbase = (size_t)id * 4096;
#pragma unroll
    for (int i = 0; i < 4; i++)
#pragma unroll
        for (int j = 0; j < 4; j++) g_g2[gbase + (r0 + i) * 64 + c0 + j] = -acc[i][j];
    __syncthreads();

    // dx1 = (G2 @ w2^T) * silu'(x1)  -> HH
    ZERO_ACC(acc);
    mm64<false, true>(G2, W2, acc, r0, c0);
#pragma unroll
    for (int i = 0; i < 4; i++)
#pragma unroll
        for (int j = 0; j < 4; j++) {
            float x = X1[(r0 + i) * 65 + c0 + j];
            float sg = sigmoidf_(x);
            HH[(r0 + i) * 65 + c0 + j] = acc[i][j] * sg * (1.f + x * (1.f - sg));
        }
    __syncthreads();

    // g1 = kc^T @ dx1  (store -g1)
    ZERO_ACC(acc);
    mm64<true, false>(KC, HH, acc, r0, c0);
#pragma unroll
    for (int i = 0; i < 4; i++)
#pragma unroll
        for (int j = 0; j < 4; j++) g_g1[gbase + (r0 + i) * 64 + c0 + j] = -acc[i][j];
}

// ---------------- K5: double assoc-scan over n=128 chunks; outputs W_eff = w + upd ----------------
__global__ __launch_bounds__(256) void scan_kernel(const float* __restrict__ w1,
                                                   const float* __restrict__ w2) {
    int bh = blockIdx.y;
    int idx = blockIdx.x * 256 + threadIdx.x;   // 0..4095 element of 64x64
    int b = bh >> 3, h = bh & 7;
    float w1v = w1[idx], w2v = w2[idx];
    float m1 = 0.f, u1 = 0.f, m2 = 0.f, u2 = 0.f;
    size_t base = ((size_t)bh * N_) * 4096 + idx;
    for (int nn = 0; nn < N_; nn++) {
        float mg = g_mom[((size_t)b * N_ + nn) * H_ + h];
        float dc = g_dec[((size_t)b * N_ + nn) * H_ + h];
        size_t off = base + (size_t)nn * 4096;
        float s1 = g_g1[off], s2 = g_g2[off];
        m1 = mg * m1 + s1; u1 = (1.f - dc) * u1 + m1; g_g1[off] = w1v + u1;
        m2 = mg * m2 + s2; u2 = (1.f - dc) * u2 + m2; g_g2[off] = w2v + u2;
    }
}

// ---------------- zero first 63 rows of g_vals per batch (causal shift pad) ----------------
__global__ void zero_pad_kernel() {
    int idx = blockIdx.x * 256 + threadIdx.x;
    const int per = 63 * DIM_;
    if (idx < B_ * per) {
        int b = idx / per, r = idx % per;
        g_vals[(size_t)b * T_ * DIM_ + r] = 0.f;
    }
}

// ---------------- K6: retrieve — fast-weight MLP + head rmsnorm + gate ----------------
__global__ __launch_bounds__(256) void retrieve_kernel(const float* __restrict__ gamma) {
    int id = blockIdx.x;               // bh*N_ + nn
    int bh = id >> 7, nn = id & 127;
    int b = bh >> 3, h = bh & 7;
    extern __shared__ float sm[];
    float* Q = sm;                // q chunk [64][65]
    float* Y = Q + 64 * 65;       // W1eff then y
    float* W2e = Y + 64 * 65;
    float* X = W2e + 64 * 65;
    __shared__ float rowscale[64];
    int tid = threadIdx.x;
    int j0 = nn * C_;
    size_t gbase = (size_t)id * 4096;
    for (int idx = tid; idx < 4096; idx += 256) {
        int ci = idx >> 6, a = idx & 63;
        int i = j0 + ci + 63;   // output-token index == s-row index
        Q[ci * 65 + a] = (i < T_) ? g_q[((size_t)b * T_ + i) * DIM_ + h * 64 + a] : 0.f;
        Y[ci * 65 + a] = g_g1[gbase + idx];
        W2e[ci * 65 + a] = g_g2[gbase + idx];
    }
    __syncthreads();
    int r0 = (tid >> 4) << 2, c0 = (tid & 15) << 2;
    float acc[4][4];

    ZERO_ACC(acc);
    mm64<false, false>(Q, Y, acc, r0, c0);
#pragma unroll
    for (int i = 0; i < 4; i++)
#pragma unroll
        for (int j = 0; j < 4; j++) {
            float x = acc[i][j];
            X[(r0 + i) * 65 + c0 + j] = x * sigmoidf_(x);
        }
    __syncthreads();

    ZERO_ACC(acc);
    mm64<false, false>(X, W2e, acc, r0, c0);
#pragma unroll
    for (int i = 0; i < 4; i++)
#pragma unroll
        for (int j = 0; j < 4; j++) Y[(r0 + i) * 65 + c0 + j] = acc[i][j];
    __syncthreads();

    if (tid < 64) {
        float ss = 0.f;
        for (int j = 0; j < 64; j++) { float y = Y[tid * 65 + j]; ss += y * y; }
        int i = j0 + tid + 63;
        float gate = (i < T_) ? g_gate[((size_t)b * T_ + i) * H_ + h] : 0.f;
        rowscale[tid] = rsqrtf(ss * (1.f / 64.f) + EPSV) * gate;
    }
    __syncthreads();
    for (int idx = tid; idx < 4096; idx += 256) {
        int ci = idx >> 6, jd = idx & 63;
        int i = j0 + ci + 63;
        if (i < T_)
            g_vals[((size_t)b * T_ + i) * DIM_ + h * 64 + jd] =
                Y[ci * 65 + jd] * rowscale[ci] * (gamma[h * 64 + jd] + 1.f);
    }
}

// ---------------- launch ----------------
extern "C" void kernel_launch(void* const* d_in, const int* in_sizes, int n_in,
                              void* d_out, int out_size) {
    const float* seq      = (const float*)d_in[0];
    const float* w1       = (const float*)d_in[1];
    const float* w2       = (const float*)d_in[2];
    const float* Wq       = (const float*)d_in[3];
    const float* Wkv      = (const float*)d_in[4];
    const float* Wstep    = (const float*)d_in[5];
    const float* Wmom     = (const float*)d_in[6];
    const float* Wdecay   = (const float*)d_in[7];
    const float* Wgate    = (const float*)d_in[8];
    const float* Wcombine = (const float*)d_in[9];
    const float* gamma    = (const float*)d_in[10];
    float* out = (float*)d_out;
    (void)in_sizes; (void)n_in; (void)out_size;

    cudaFuncSetAttribute(chunk_grad_kernel, cudaFuncAttributeMaxDynamicSharedMemorySize,
                         5 * 64 * 65 * 4);
    cudaFuncSetAttribute(retrieve_kernel, cudaFuncAttributeMaxDynamicSharedMemorySize,
                         4 * 64 * 65 * 4);

    float *p_s, *p_kv, *p_q, *p_vals;
    cudaGetSymbolAddress((void**)&p_s, g_s);
    cudaGetSymbolAddress((void**)&p_kv, g_kv);
    cudaGetSymbolAddress((void**)&p_q, g_q);
    cudaGetSymbolAddress((void**)&p_vals, g_vals);

    rmsnorm_kernel<<<B_ * T_, 256>>>(seq);
    proj_kernel<<<B_ * N_, 256>>>(Wstep, Wgate, Wmom, Wdecay);
    sgemm128<<<dim3(2 * DIM_ / 128, B_ * T_ / 128), 256>>>(p_s, Wkv, p_kv, B_ * T_, 2 * DIM_, DIM_);
    sgemm128<<<dim3(DIM_ / 128, B_ * T_ / 128), 256>>>(p_s, Wq, p_q, B_ * T_, DIM_, DIM_);
    chunk_grad_kernel<<<BH_ * N_, 256, 5 * 64 * 65 * 4>>>(w1, w2);
    scan_kernel<<<dim3(16, BH_), 256>>>(w1, w2);
    zero_pad_kernel<<<(B_ * 63 * DIM_ + 255) / 256, 256>>>();
    retrieve_kernel<<<BH_ * N_, 256, 4 * 64 * 65 * 4>>>(gamma);
    sgemm128<<<dim3(DIM_ / 128, B_ * T_ / 128), 256>>>(p_vals, Wcombine, out, B_ * T_, DIM_, DIM_);
}

// round 6
// speedup vs baseline: 1.7000x; 1.7000x over previous
#include <cuda_runtime.h>
#include <cstdint>
#include <cstddef>

#define B_ 4
#define T_ 8192
#define DIM_ 512
#define H_ 8
#define D_ 64
#define C_ 64
#define N_ 128
#define BH_ 32
#define EPSV 1.1920929e-07f
#define MAX_LR 0.01f

// ---------------- scratch (static device globals; no allocations) ----------------
__device__ float g_s  [(size_t)B_*T_*DIM_];     // rmsnorm(seq)
__device__ float g_kv [(size_t)B_*T_*2*DIM_];   // [k | v]
__device__ float g_q  [(size_t)B_*T_*DIM_];     // s @ Wq
__device__ float g_g1 [(size_t)BH_*N_*D_*D_];   // -grad w1 -> W1eff after scan
__device__ float g_g2 [(size_t)BH_*N_*D_*D_];   // -grad w2 -> W2eff after scan
__device__ float g_vals[(size_t)B_*T_*DIM_];    // merged per-head values (shifted)
__device__ float g_lr  [(size_t)B_*T_*H_];
__device__ float g_gate[(size_t)B_*T_*H_];
__device__ float g_mom [(size_t)B_*N_*H_];
__device__ float g_dec [(size_t)B_*N_*H_];

__device__ __forceinline__ float sigmoidf_(float x) { return 1.f / (1.f + expf(-x)); }

// ---------------- K1: rmsnorm over dim=512 ----------------
__global__ __launch_bounds__(256) void rmsnorm_kernel(const float* __restrict__ seq) {
    size_t row = blockIdx.x;
    const float* in = seq + row * DIM_;
    float* out = g_s + row * DIM_;
    int tid = threadIdx.x;
    float v0 = in[tid], v1 = in[tid + 256];
    float ss = v0 * v0 + v1 * v1;
#pragma unroll
    for (int o = 16; o; o >>= 1) ss += __shfl_xor_sync(0xffffffffu, ss, o);
    __shared__ float wsum[8];
    if ((tid & 31) == 0) wsum[tid >> 5] = ss;
    __syncthreads();
    float tot = 0.f;
#pragma unroll
    for (int w = 0; w < 8; w++) tot += wsum[w];
    float sc = rsqrtf(tot * (1.f / DIM_) + EPSV);
    out[tid] = v0 * sc;
    out[tid + 256] = v1 * sc;
}

// ---------------- K2: per-token lr/gate projections + per-chunk mom/decay ----------------
__global__ __launch_bounds__(256) void proj_kernel(const float* __restrict__ Wstep,
                                                   const float* __restrict__ Wgate,
                                                   const float* __restrict__ Wmom,
                                                   const float* __restrict__ Wdecay) {
    int blk = blockIdx.x;              // b*N_ + nn
    int b = blk >> 7, nn = blk & 127;
    size_t tb = (size_t)b * T_ + (size_t)nn * C_;
    int tid = threadIdx.x, lane = tid & 31, w = tid >> 5;

    for (int tk = w; tk < C_; tk += 8) {
        const float* srow = g_s + (tb + tk) * DIM_;
        float acc[16];
#pragma unroll
        for (int q = 0; q < 16; q++) acc[q] = 0.f;
        for (int p = lane; p < DIM_; p += 32) {
            float sv = srow[p];
            const float* ws = Wstep + p * H_;
            const float* wg = Wgate + p * H_;
#pragma unroll
            for (int hh = 0; hh < 8; hh++) {
                acc[hh]     += sv * ws[hh];
                acc[8 + hh] += sv * wg[hh];
            }
        }
#pragma unroll
        for (int q = 0; q < 16; q++)
#pragma unroll
            for (int o = 16; o; o >>= 1) acc[q] += __shfl_xor_sync(0xffffffffu, acc[q], o);
        if (lane == 0) {
#pragma unroll
            for (int hh = 0; hh < 8; hh++) {
                g_lr  [(tb + tk) * H_ + hh] = sigmoidf_(acc[hh]) * MAX_LR;
                g_gate[(tb + tk) * H_ + hh] = sigmoidf_(acc[8 + hh]);
            }
        }
    }

    __shared__ float ssum[DIM_];
    for (int p = tid; p < DIM_; p += 256) {
        float a = 0.f;
        for (int tk = 0; tk < C_; tk++) a += g_s[(tb + tk) * DIM_ + p];
        ssum[p] = a * (1.f / C_);
    }
    __syncthreads();
    if (w < 8) {
        float am = 0.f, ad = 0.f;
        for (int p = lane; p < DIM_; p += 32) {
            am += ssum[p] * Wmom[p * H_ + w];
            ad += ssum[p] * Wdecay[p * H_ + w];
        }
#pragma unroll
        for (int o = 16; o; o >>= 1) {
            am += __shfl_xor_sync(0xffffffffu, am, o);
            ad += __shfl_xor_sync(0xffffffffu, ad, o);
        }
        if (lane == 0) {
            g_mom[((size_t)b * N_ + nn) * H_ + w] = sigmoidf_(am);
            g_dec[((size_t)b * N_ + nn) * H_ + w] = sigmoidf_(ad);
        }
    }
}

// ---------------- tensor-core GEMM: 3xTF32 split, C = A[MxK] @ B[KxN] row-major ----------------
__device__ __forceinline__ uint32_t f2tf(float x) {
    uint32_t r;
    asm("cvt.rna.tf32.f32 %0, %1;" : "=r"(r) : "f"(x));
    return r;
}

__device__ __forceinline__ void mma_tf32(float c[4], const uint32_t a[4],
                                         uint32_t b0, uint32_t b1) {
    asm volatile(
        "mma.sync.aligned.m16n8k8.row.col.f32.tf32.tf32.f32 "
        "{%0,%1,%2,%3},{%4,%5,%6,%7},{%8,%9},{%0,%1,%2,%3};"
        : "+f"(c[0]), "+f"(c[1]), "+f"(c[2]), "+f"(c[3])
        : "r"(a[0]), "r"(a[1]), "r"(a[2]), "r"(a[3]), "r"(b0), "r"(b1));
}

#define ALD 36      // A smem leading dim (pad: frag loads conflict-free)
#define BLD 136     // B smem leading dim
#define A_SZ (128 * ALD)
#define B_SZ (32 * BLD)
#define GEMM_SMEM ((2 * A_SZ + 2 * B_SZ) * 4)

__global__ __launch_bounds__(256) void gemm_tf32(const float* __restrict__ A,
                                                 const float* __restrict__ B,
                                                 float* __restrict__ C,
                                                 int M, int N, int K) {
    extern __shared__ uint32_t smem_u[];
    uint32_t* Ah = smem_u;
    uint32_t* Al = Ah + A_SZ;
    uint32_t* Bh = Al + A_SZ;
    uint32_t* Bl = Bh + B_SZ;

    int tid = threadIdx.x;
    int lane = tid & 31, warp = tid >> 5;
    int brow = blockIdx.y * 128, bcol = blockIdx.x * 128;
    int wm = (warp >> 1) * 32, wn = (warp & 1) * 64;
    int g = lane >> 2, tg = lane & 3;

    float acc[2][8][4];
#pragma unroll
    for (int mi = 0; mi < 2; mi++)
#pragma unroll
        for (int ni = 0; ni < 8; ni++)
#pragma unroll
            for (int e = 0; e < 4; e++) acc[mi][ni][e] = 0.f;

    for (int kt = 0; kt < K; kt += 32) {
        __syncthreads();
#pragma unroll
        for (int p = 0; p < 4; p++) {
            int i = p * 256 + tid;
            int r = i >> 3, c = (i & 7) << 2;
            float4 av = *(const float4*)(A + (size_t)(brow + r) * K + kt + c);
            float af[4] = {av.x, av.y, av.z, av.w};
#pragma unroll
            for (int e = 0; e < 4; e++) {
                uint32_t hi = f2tf(af[e]);
                Ah[r * ALD + c + e] = hi;
                Al[r * ALD + c + e] = f2tf(af[e] - __uint_as_float(hi));
            }
            int rb = i >> 5, cb = (i & 31) << 2;
            float4 bv = *(const float4*)(B + (size_t)(kt + rb) * N + bcol + cb);
            float bf[4] = {bv.x, bv.y, bv.z, bv.w};
#pragma unroll
            for (int e = 0; e < 4; e++) {
                uint32_t hi = f2tf(bf[e]);
                Bh[rb * BLD + cb + e] = hi;
                Bl[rb * BLD + cb + e] = f2tf(bf[e] - __uint_as_float(hi));
            }
        }
        __syncthreads();

#pragma unroll
        for (int kk = 0; kk < 4; kk++) {
            int k8 = kk * 8;
            uint32_t ah[2][4], al[2][4];
#pragma unroll
            for (int mi = 0; mi < 2; mi++) {
                int r0 = (wm + mi * 16 + g) * ALD + k8 + tg;
                int r1 = r0 + 8 * ALD;
                ah[mi][0] = Ah[r0];     ah[mi][1] = Ah[r1];
                ah[mi][2] = Ah[r0 + 4]; ah[mi][3] = Ah[r1 + 4];
                al[mi][0] = Al[r0];     al[mi][1] = Al[r1];
                al[mi][2] = Al[r0 + 4]; al[mi][3] = Al[r1 + 4];
            }
#pragma unroll
            for (int ni = 0; ni < 8; ni++) {
                int nb = (k8 + tg) * BLD + wn + ni * 8 + g;
                uint32_t bh0 = Bh[nb], bh1 = Bh[nb + 4 * BLD];
                uint32_t bl0 = Bl[nb], bl1 = Bl[nb + 4 * BLD];
#pragma unroll
                for (int mi = 0; mi < 2; mi++) {
                    mma_tf32(acc[mi][ni], ah[mi], bh0, bh1);
                    mma_tf32(acc[mi][ni], ah[mi], bl0, bl1);
                    mma_tf32(acc[mi][ni], al[mi], bh0, bh1);
                }
            }
        }
    }

#pragma unroll
    for (int mi = 0; mi < 2; mi++)
#pragma unroll
        for (int ni = 0; ni < 8; ni++) {
            int r = brow + wm + mi * 16 + g;
            int cx = bcol + wn + ni * 8 + tg * 2;
            float2 lo = {acc[mi][ni][0], acc[mi][ni][1]};
            float2 hi = {acc[mi][ni][2], acc[mi][ni][3]};
            *(float2*)(C + (size_t)r * N + cx) = lo;
            *(float2*)(C + (size_t)(r + 8) * N + cx) = hi;
        }
}

// ---------------- shared-memory 64x64x64 matmul helper (padded ld=65) ----------------
template <bool TA, bool TB>
__device__ __forceinline__ void mm64(const float* A, const float* B, float acc[4][4],
                                     int r0, int c0) {
#pragma unroll 4
    for (int k = 0; k < 64; k++) {
        float a[4], bv[4];
#pragma unroll
        for (int i = 0; i < 4; i++) a[i] = TA ? A[k * 65 + r0 + i] : A[(r0 + i) * 65 + k];
#pragma unroll
        for (int j = 0; j < 4; j++) bv[j] = TB ? B[(c0 + j) * 65 + k] : B[k * 65 + c0 + j];
#pragma unroll
        for (int i = 0; i < 4; i++)
#pragma unroll
            for (int j = 0; j < 4; j++) acc[i][j] += a[i] * bv[j];
    }
}

#define ZERO_ACC(acc)                         \
    _Pragma("unroll") for (int i = 0; i < 4; i++) \
    _Pragma("unroll") for (int j = 0; j < 4; j++) acc[i][j] = 0.f;

// ---------------- K4: per-chunk MLP gradients (surprises = -grad) ----------------
__global__ __launch_bounds__(256) void chunk_grad_kernel(const float* __restrict__ w1,
                                                         const float* __restrict__ w2) {
    int id = blockIdx.x;               // bh*N_ + nn
    int bh = id >> 7, nn = id & 127;
    int b = bh >> 3, h = bh & 7;
    size_t tb = (size_t)b * T_ + (size_t)nn * C_;
    extern __shared__ float sm[];
    float* KC = sm;
    float* G2 = KC + 64 * 65;
    float* W2 = G2 + 64 * 65;
    float* X1 = W2 + 64 * 65;
    float* HH = X1 + 64 * 65;
    __shared__ float lrs[64];
    int tid = threadIdx.x;
    if (tid < 64) lrs[tid] = g_lr[(tb + tid) * H_ + h];
    for (int idx = tid; idx < 4096; idx += 256) {
        int i = idx >> 6, j = idx & 63;
        KC[i * 65 + j] = g_kv[(tb + i) * (2 * DIM_) + h * 64 + j];
        G2[i * 65 + j] = w1[idx];
        W2[i * 65 + j] = w2[idx];
    }
    __syncthreads();
    int r0 = (tid >> 4) << 2;
    int c0 = (tid & 15) << 2;
    float acc[4][4];

    ZERO_ACC(acc);
    mm64<false, false>(KC, G2, acc, r0, c0);
#pragma unroll
    for (int i = 0; i < 4; i++)
#pragma unroll
        for (int j = 0; j < 4; j++) {
            float x = acc[i][j];
            X1[(r0 + i) * 65 + c0 + j] = x;
            HH[(r0 + i) * 65 + c0 + j] = x * sigmoidf_(x);
        }
    __syncthreads();

    ZERO_ACC(acc);
    mm64<false, false>(HH, W2, acc, r0, c0);
#pragma unroll
    for (int i = 0; i < 4; i++)
#pragma unroll
        for (int j = 0; j < 4; j++) {
            int row = r0 + i, col = c0 + j;
            float vc = g_kv[(tb + row) * (2 * DIM_) + DIM_ + h * 64 + col];
            G2[row * 65 + col] = (2.f / 64.f) * lrs[row] * (acc[i][j] - vc);
        }
    __syncthreads();

    ZERO_ACC(acc);
    mm64<true, false>(HH, G2, acc, r0, c0);
    size_t gbase = (size_t)id * 4096;
#pragma unroll
    for (int i = 0; i < 4; i++)
#pragma unroll
        for (int j = 0; j < 4; j++) g_g2[gbase + (r0 + i) * 64 + c0 + j] = -acc[i][j];
    __syncthreads();

    ZERO_ACC(acc);
    mm64<false, true>(G2, W2, acc, r0, c0);
#pragma unroll
    for (int i = 0; i < 4; i++)
#pragma unroll
        for (int j = 0; j < 4; j++) {
            float x = X1[(r0 + i) * 65 + c0 + j];
            float sg = sigmoidf_(x);
            HH[(r0 + i) * 65 + c0 + j] = acc[i][j] * sg * (1.f + x * (1.f - sg));
        }
    __syncthreads();

    ZERO_ACC(acc);
    mm64<true, false>(KC, HH, acc, r0, c0);
#pragma unroll
    for (int i = 0; i < 4; i++)
#pragma unroll
        for (int j = 0; j < 4; j++) g_g1[gbase + (r0 + i) * 64 + c0 + j] = -acc[i][j];
}

// ---------------- K5: double assoc-scan over n=128 chunks ----------------
__global__ __launch_bounds__(256) void scan_kernel(const float* __restrict__ w1,
                                                   const float* __restrict__ w2) {
    int bh = blockIdx.y;
    int idx = blockIdx.x * 256 + threadIdx.x;
    int b = bh >> 3, h = bh & 7;
    float w1v = w1[idx], w2v = w2[idx];
    float m1 = 0.f, u1 = 0.f, m2 = 0.f, u2 = 0.f;
    size_t base = ((size_t)bh * N_) * 4096 + idx;
    for (int nn = 0; nn < N_; nn++) {
        float mg = g_mom[((size_t)b * N_ + nn) * H_ + h];
        float dc = g_dec[((size_t)b * N_ + nn) * H_ + h];
        size_t off = base + (size_t)nn * 4096;
        float s1 = g_g1[off], s2 = g_g2[off];
        m1 = mg * m1 + s1; u1 = (1.f - dc) * u1 + m1; g_g1[off] = w1v + u1;
        m2 = mg * m2 + s2; u2 = (1.f - dc) * u2 + m2; g_g2[off] = w2v + u2;
    }
}

// ---------------- zero first 63 rows of g_vals per batch ----------------
__global__ void zero_pad_kernel() {
    int idx = blockIdx.x * 256 + threadIdx.x;
    const int per = 63 * DIM_;
    if (idx < B_ * per) {
        int b = idx / per, r = idx % per;
        g_vals[(size_t)b * T_ * DIM_ + r] = 0.f;
    }
}

// ---------------- K6: retrieve ----------------
__global__ __launch_bounds__(256) void retrieve_kernel(const float* __restrict__ gamma) {
    int id = blockIdx.x;
    int bh = id >> 7, nn = id & 127;
    int b = bh >> 3, h = bh & 7;
    extern __shared__ float sm[];
    float* Q = sm;
    float* Y = Q + 64 * 65;
    float* W2e = Y + 64 * 65;
    float* X = W2e + 64 * 65;
    __shared__ float rowscale[64];
    int tid = threadIdx.x;
    int j0 = nn * C_;
    size_t gbase = (size_t)id * 4096;
    for (int idx = tid; idx < 4096; idx += 256) {
        int ci = idx >> 6, a = idx & 63;
        int i = j0 + ci + 63;
        Q[ci * 65 + a] = (i < T_) ? g_q[((size_t)b * T_ + i) * DIM_ + h * 64 + a] : 0.f;
        Y[ci * 65 + a] = g_g1[gbase + idx];
        W2e[ci * 65 + a] = g_g2[gbase + idx];
    }
    __syncthreads();
    int r0 = (tid >> 4) << 2, c0 = (tid & 15) << 2;
    float acc[4][4];

    ZERO_ACC(acc);
    mm64<false, false>(Q, Y, acc, r0, c0);
#pragma unroll
    for (int i = 0; i < 4; i++)
#pragma unroll
        for (int j = 0; j < 4; j++) {
            float x = acc[i][j];
            X[(r0 + i) * 65 + c0 + j] = x * sigmoidf_(x);
        }
    __syncthreads();

    ZERO_ACC(acc);
    mm64<false, false>(X, W2e, acc, r0, c0);
#pragma unroll
    for (int i = 0; i < 4; i++)
#pragma unroll
        for (int j = 0; j < 4; j++) Y[(r0 + i) * 65 + c0 + j] = acc[i][j];
    __syncthreads();

    if (tid < 64) {
        float ss = 0.f;
        for (int j = 0; j < 64; j++) { float y = Y[tid * 65 + j]; ss += y * y; }
        int i = j0 + tid + 63;
        float gate = (i < T_) ? g_gate[((size_t)b * T_ + i) * H_ + h] : 0.f;
        rowscale[tid] = rsqrtf(ss * (1.f / 64.f) + EPSV) * gate;
    }
    __syncthreads();
    for (int idx = tid; idx < 4096; idx += 256) {
        int ci = idx >> 6, jd = idx & 63;
        int i = j0 + ci + 63;
        if (i < T_)
            g_vals[((size_t)b * T_ + i) * DIM_ + h * 64 + jd] =
                Y[ci * 65 + jd] * rowscale[ci] * (gamma[h * 64 + jd] + 1.f);
    }
}

// ---------------- launch ----------------
extern "C" void kernel_launch(void* const* d_in, const int* in_sizes, int n_in,
                              void* d_out, int out_size) {
    const float* seq      = (const float*)d_in[0];
    const float* w1       = (const float*)d_in[1];
    const float* w2       = (const float*)d_in[2];
    const float* Wq       = (const float*)d_in[3];
    const float* Wkv      = (const float*)d_in[4];
    const float* Wstep    = (const float*)d_in[5];
    const float* Wmom     = (const float*)d_in[6];
    const float* Wdecay   = (const float*)d_in[7];
    const float* Wgate    = (const float*)d_in[8];
    const float* Wcombine = (const float*)d_in[9];
    const float* gamma    = (const float*)d_in[10];
    float* out = (float*)d_out;
    (void)in_sizes; (void)n_in; (void)out_size;

    cudaFuncSetAttribute(chunk_grad_kernel, cudaFuncAttributeMaxDynamicSharedMemorySize,
                         5 * 64 * 65 * 4);
    cudaFuncSetAttribute(retrieve_kernel, cudaFuncAttributeMaxDynamicSharedMemorySize,
                         4 * 64 * 65 * 4);
    cudaFuncSetAttribute(gemm_tf32, cudaFuncAttributeMaxDynamicSharedMemorySize, GEMM_SMEM);

    float *p_s, *p_kv, *p_q, *p_vals;
    cudaGetSymbolAddress((void**)&p_s, g_s);
    cudaGetSymbolAddress((void**)&p_kv, g_kv);
    cudaGetSymbolAddress((void**)&p_q, g_q);
    cudaGetSymbolAddress((void**)&p_vals, g_vals);

    rmsnorm_kernel<<<B_ * T_, 256>>>(seq);
    proj_kernel<<<B_ * N_, 256>>>(Wstep, Wgate, Wmom, Wdecay);
    gemm_tf32<<<dim3(2 * DIM_ / 128, B_ * T_ / 128), 256, GEMM_SMEM>>>(p_s, Wkv, p_kv,
                                                                       B_ * T_, 2 * DIM_, DIM_);
    gemm_tf32<<<dim3(DIM_ / 128, B_ * T_ / 128), 256, GEMM_SMEM>>>(p_s, Wq, p_q,
                                                                   B_ * T_, DIM_, DIM_);
    chunk_grad_kernel<<<BH_ * N_, 256, 5 * 64 * 65 * 4>>>(w1, w2);
    scan_kernel<<<dim3(16, BH_), 256>>>(w1, w2);
    zero_pad_kernel<<<(B_ * 63 * DIM_ + 255) / 256, 256>>>();
    retrieve_kernel<<<BH_ * N_, 256, 4 * 64 * 65 * 4>>>(gamma);
    gemm_tf32<<<dim3(DIM_ / 128, B_ * T_ / 128), 256, GEMM_SMEM>>>(p_vals, Wcombine, out,
                                                                   B_ * T_, DIM_, DIM_);
}

// round 7
// speedup vs baseline: 1.8229x; 1.0723x over previous
#include <cuda_runtime.h>
#include <cstdint>
#include <cstddef>

#define B_ 4
#define T_ 8192
#define DIM_ 512
#define H_ 8
#define D_ 64
#define C_ 64
#define N_ 128
#define BH_ 32
#define EPSV 1.1920929e-07f
#define MAX_LR 0.01f

// ---------------- scratch (static device globals; no allocations) ----------------
__device__ float g_s  [(size_t)B_*T_*DIM_];     // rmsnorm(seq) fp32 (for proj)
__device__ uint32_t g_sh[(size_t)B_*T_*DIM_];   // rmsnorm(seq) tf32 hi
__device__ uint32_t g_sl[(size_t)B_*T_*DIM_];   // tf32 lo
__device__ float g_kv [(size_t)B_*T_*2*DIM_];   // [k | v]
__device__ float g_q  [(size_t)B_*T_*DIM_];     // s @ Wq
__device__ float g_g1 [(size_t)BH_*N_*D_*D_];   // -grad w1 -> W1eff after scan
__device__ float g_g2 [(size_t)BH_*N_*D_*D_];   // -grad w2 -> W2eff after scan
__device__ uint32_t g_vh[(size_t)B_*T_*DIM_];   // merged per-head values tf32 hi
__device__ uint32_t g_vl[(size_t)B_*T_*DIM_];   // tf32 lo
__device__ float g_lr  [(size_t)B_*T_*H_];
__device__ float g_gate[(size_t)B_*T_*H_];
__device__ float g_mom [(size_t)B_*N_*H_];
__device__ float g_dec [(size_t)B_*N_*H_];
// preconverted weights
__device__ uint32_t g_wkvh[DIM_*2*DIM_], g_wkvl[DIM_*2*DIM_];
__device__ uint32_t g_wqh [DIM_*DIM_],   g_wql [DIM_*DIM_];
__device__ uint32_t g_wch [DIM_*DIM_],   g_wcl [DIM_*DIM_];

__device__ __forceinline__ float sigmoidf_(float x) { return 1.f / (1.f + expf(-x)); }

__device__ __forceinline__ uint32_t f2tf(float x) {
    uint32_t r;
    asm("cvt.rna.tf32.f32 %0, %1;" : "=r"(r) : "f"(x));
    return r;
}

__device__ __forceinline__ void mma_tf32(float c[4], const uint32_t a[4],
                                         uint32_t b0, uint32_t b1) {
    asm volatile(
        "mma.sync.aligned.m16n8k8.row.col.f32.tf32.tf32.f32 "
        "{%0,%1,%2,%3},{%4,%5,%6,%7},{%8,%9},{%0,%1,%2,%3};"
        : "+f"(c[0]), "+f"(c[1]), "+f"(c[2]), "+f"(c[3])
        : "r"(a[0]), "r"(a[1]), "r"(a[2]), "r"(a[3]), "r"(b0), "r"(b1));
}

__device__ __forceinline__ void cp16(uint32_t dst, const void* src) {
    asm volatile("cp.async.ca.shared.global [%0], [%1], 16;" :: "r"(dst), "l"(src));
}

// ---------------- K1: rmsnorm over dim=512, emits fp32 + tf32 hi/lo ----------------
__global__ __launch_bounds__(256) void rmsnorm_kernel(const float* __restrict__ seq) {
    size_t row = blockIdx.x;
    const float* in = seq + row * DIM_;
    int tid = threadIdx.x;
    float v0 = in[tid], v1 = in[tid + 256];
    float ss = v0 * v0 + v1 * v1;
#pragma unroll
    for (int o = 16; o; o >>= 1) ss += __shfl_xor_sync(0xffffffffu, ss, o);
    __shared__ float wsum[8];
    if ((tid & 31) == 0) wsum[tid >> 5] = ss;
    __syncthreads();
    float tot = 0.f;
#pragma unroll
    for (int w = 0; w < 8; w++) tot += wsum[w];
    float sc = rsqrtf(tot * (1.f / DIM_) + EPSV);
    float o0 = v0 * sc, o1 = v1 * sc;
    size_t base = row * DIM_;
    g_s[base + tid] = o0;
    g_s[base + tid + 256] = o1;
    uint32_t h0 = f2tf(o0), h1 = f2tf(o1);
    g_sh[base + tid] = h0;        g_sl[base + tid] = f2tf(o0 - __uint_as_float(h0));
    g_sh[base + tid + 256] = h1;  g_sl[base + tid + 256] = f2tf(o1 - __uint_as_float(h1));
}

// ---------------- weight preconvert ----------------
__global__ void cvt_kernel(const float* __restrict__ src, uint32_t* __restrict__ dh,
                           uint32_t* __restrict__ dl, int n) {
    int i = blockIdx.x * 256 + threadIdx.x;
    if (i < n) {
        float v = src[i];
        uint32_t hi = f2tf(v);
        dh[i] = hi;
        dl[i] = f2tf(v - __uint_as_float(hi));
    }
}

// ---------------- K2: per-token lr/gate projections + per-chunk mom/decay ----------------
__global__ __launch_bounds__(256) void proj_kernel(const float* __restrict__ Wstep,
                                                   const float* __restrict__ Wgate,
                                                   const float* __restrict__ Wmom,
                                                   const float* __restrict__ Wdecay) {
    int blk = blockIdx.x;              // b*N_ + nn
    int b = blk >> 7, nn = blk & 127;
    size_t tb = (size_t)b * T_ + (size_t)nn * C_;
    int tid = threadIdx.x, lane = tid & 31, w = tid >> 5;

    for (int tk = w; tk < C_; tk += 8) {
        const float* srow = g_s + (tb + tk) * DIM_;
        float acc[16];
#pragma unroll
        for (int q = 0; q < 16; q++) acc[q] = 0.f;
        for (int p = lane; p < DIM_; p += 32) {
            float sv = srow[p];
            const float* ws = Wstep + p * H_;
            const float* wg = Wgate + p * H_;
#pragma unroll
            for (int hh = 0; hh < 8; hh++) {
                acc[hh]     += sv * ws[hh];
                acc[8 + hh] += sv * wg[hh];
            }
        }
#pragma unroll
        for (int q = 0; q < 16; q++)
#pragma unroll
            for (int o = 16; o; o >>= 1) acc[q] += __shfl_xor_sync(0xffffffffu, acc[q], o);
        if (lane == 0) {
#pragma unroll
            for (int hh = 0; hh < 8; hh++) {
                g_lr  [(tb + tk) * H_ + hh] = sigmoidf_(acc[hh]) * MAX_LR;
                g_gate[(tb + tk) * H_ + hh] = sigmoidf_(acc[8 + hh]);
            }
        }
    }

    __shared__ float ssum[DIM_];
    for (int p = tid; p < DIM_; p += 256) {
        float a = 0.f;
        for (int tk = 0; tk < C_; tk++) a += g_s[(tb + tk) * DIM_ + p];
        ssum[p] = a * (1.f / C_);
    }
    __syncthreads();
    if (w < 8) {
        float am = 0.f, ad = 0.f;
        for (int p = lane; p < DIM_; p += 32) {
            am += ssum[p] * Wmom[p * H_ + w];
            ad += ssum[p] * Wdecay[p * H_ + w];
        }
#pragma unroll
        for (int o = 16; o; o >>= 1) {
            am += __shfl_xor_sync(0xffffffffu, am, o);
            ad += __shfl_xor_sync(0xffffffffu, ad, o);
        }
        if (lane == 0) {
            g_mom[((size_t)b * N_ + nn) * H_ + w] = sigmoidf_(am);
            g_dec[((size_t)b * N_ + nn) * H_ + w] = sigmoidf_(ad);
        }
    }
}

// ---------------- gemm_tc: cp.async double-buffered, preconverted tf32 hi/lo ----------------
#define SA_LD 36
#define SB_LD 136
#define SA_SZ (128 * SA_LD)
#define SB_SZ (32 * SB_LD)
#define STAGE_SZ (2 * SA_SZ + 2 * SB_SZ)
#define GEMM_SMEM (2 * STAGE_SZ * 4)

__device__ __forceinline__ void gemm_issue(uint32_t sbase, const uint32_t* __restrict__ Ah,
                                           const uint32_t* __restrict__ Al,
                                           const uint32_t* __restrict__ Bh,
                                           const uint32_t* __restrict__ Bl,
                                           int brow, int bcol, int kt, int K, int N, int tid) {
    int ra = tid >> 3, ca = (tid & 7) << 2;
    int rb = tid >> 5, cb = (tid & 31) << 2;
#pragma unroll
    for (int p = 0; p < 4; p++) {
        int r = p * 32 + ra;
        size_t ga = (size_t)(brow + r) * K + kt + ca;
        uint32_t da = sbase + (r * SA_LD + ca) * 4;
        cp16(da, Ah + ga);
        cp16(da + SA_SZ * 4, Al + ga);
        int r2 = p * 8 + rb;
        size_t gb = (size_t)(kt + r2) * N + bcol + cb;
        uint32_t db = sbase + (2 * SA_SZ + r2 * SB_LD + cb) * 4;
        cp16(db, Bh + gb);
        cp16(db + SB_SZ * 4, Bl + gb);
    }
}

__global__ __launch_bounds__(256) void gemm_tc(const uint32_t* __restrict__ Ah,
                                               const uint32_t* __restrict__ Al,
                                               const uint32_t* __restrict__ Bh,
                                               const uint32_t* __restrict__ Bl,
                                               float* __restrict__ C,
                                               int M, int N, int K) {
    extern __shared__ uint32_t smem_u[];
    int tid = threadIdx.x;
    int lane = tid & 31, warp = tid >> 5;
    int brow = blockIdx.y * 128, bcol = blockIdx.x * 128;
    int wm = (warp >> 1) * 32, wn = (warp & 1) * 64;
    int g = lane >> 2, tg = lane & 3;
    uint32_t sbase = (uint32_t)__cvta_generic_to_shared(smem_u);

    float acc[2][8][4];
#pragma unroll
    for (int mi = 0; mi < 2; mi++)
#pragma unroll
        for (int ni = 0; ni < 8; ni++)
#pragma unroll
            for (int e = 0; e < 4; e++) acc[mi][ni][e] = 0.f;

    gemm_issue(sbase, Ah, Al, Bh, Bl, brow, bcol, 0, K, N, tid);
    asm volatile("cp.async.commit_group;");

    int KT = K >> 5;
    for (int t = 0; t < KT; t++) {
        if (t + 1 < KT) {
            gemm_issue(sbase + ((t + 1) & 1) * STAGE_SZ * 4, Ah, Al, Bh, Bl,
                       brow, bcol, (t + 1) << 5, K, N, tid);
            asm volatile("cp.async.commit_group;");
            asm volatile("cp.async.wait_group 1;");
        } else {
            asm volatile("cp.async.wait_group 0;");
        }
        __syncthreads();
        const uint32_t* st = smem_u + (t & 1) * STAGE_SZ;
        const uint32_t* sAh = st;
        const uint32_t* sAl = st + SA_SZ;
        const uint32_t* sBh = st + 2 * SA_SZ;
        const uint32_t* sBl = st + 2 * SA_SZ + SB_SZ;
#pragma unroll
        for (int kk = 0; kk < 4; kk++) {
            int k8 = kk * 8;
            uint32_t ah[2][4], al[2][4];
#pragma unroll
            for (int mi = 0; mi < 2; mi++) {
                int r0 = (wm + mi * 16 + g) * SA_LD + k8 + tg;
                int r1 = r0 + 8 * SA_LD;
                ah[mi][0] = sAh[r0];     ah[mi][1] = sAh[r1];
                ah[mi][2] = sAh[r0 + 4]; ah[mi][3] = sAh[r1 + 4];
                al[mi][0] = sAl[r0];     al[mi][1] = sAl[r1];
                al[mi][2] = sAl[r0 + 4]; al[mi][3] = sAl[r1 + 4];
            }
#pragma unroll
            for (int ni = 0; ni < 8; ni++) {
                int nb = (k8 + tg) * SB_LD + wn + ni * 8 + g;
                uint32_t bh0 = sBh[nb], bh1 = sBh[nb + 4 * SB_LD];
                uint32_t bl0 = sBl[nb], bl1 = sBl[nb + 4 * SB_LD];
#pragma unroll
                for (int mi = 0; mi < 2; mi++) {
                    mma_tf32(acc[mi][ni], ah[mi], bh0, bh1);
                    mma_tf32(acc[mi][ni], ah[mi], bl0, bl1);
                    mma_tf32(acc[mi][ni], al[mi], bh0, bh1);
                }
            }
        }
        __syncthreads();
    }

#pragma unroll
    for (int mi = 0; mi < 2; mi++)
#pragma unroll
        for (int ni = 0; ni < 8; ni++) {
            int r = brow + wm + mi * 16 + g;
            int cx = bcol + wn + ni * 8 + tg * 2;
            float2 lo = {acc[mi][ni][0], acc[mi][ni][1]};
            float2 hi = {acc[mi][ni][2], acc[mi][ni][3]};
            *(float2*)(C + (size_t)r * N + cx) = lo;
            *(float2*)(C + (size_t)(r + 8) * N + cx) = hi;
        }
}

// ---------------- tensor-core 64x64x64 from smem tf32 hi/lo (3x split) ----------------
#define CLD 68
#define BUF (64 * CLD)

template <bool TA, bool TB>
__device__ __forceinline__ void mm64_tc(const uint32_t* __restrict__ Ah,
                                        const uint32_t* __restrict__ Al,
                                        const uint32_t* __restrict__ Bh,
                                        const uint32_t* __restrict__ Bl,
                                        float acc[4][4], int m0, int n0, int g, int tg) {
#pragma unroll
    for (int ni = 0; ni < 4; ni++)
#pragma unroll
        for (int e = 0; e < 4; e++) acc[ni][e] = 0.f;
#pragma unroll 2
    for (int k8 = 0; k8 < 64; k8 += 8) {
        uint32_t ah[4], al[4];
        if (!TA) {
            int ba = (m0 + g) * CLD + k8 + tg;
            ah[0] = Ah[ba]; ah[1] = Ah[ba + 8 * CLD]; ah[2] = Ah[ba + 4]; ah[3] = Ah[ba + 8 * CLD + 4];
            al[0] = Al[ba]; al[1] = Al[ba + 8 * CLD]; al[2] = Al[ba + 4]; al[3] = Al[ba + 8 * CLD + 4];
        } else {
            int ba = (k8 + tg) * CLD + m0 + g;
            ah[0] = Ah[ba]; ah[1] = Ah[ba + 8]; ah[2] = Ah[ba + 4 * CLD]; ah[3] = Ah[ba + 4 * CLD + 8];
            al[0] = Al[ba]; al[1] = Al[ba + 8]; al[2] = Al[ba + 4 * CLD]; al[3] = Al[ba + 4 * CLD + 8];
        }
#pragma unroll
        for (int ni = 0; ni < 4; ni++) {
            uint32_t bh0, bh1, bl0, bl1;
            if (!TB) {
                int bb = (k8 + tg) * CLD + n0 + ni * 8 + g;
                bh0 = Bh[bb]; bh1 = Bh[bb + 4 * CLD];
                bl0 = Bl[bb]; bl1 = Bl[bb + 4 * CLD];
            } else {
                int bb = (n0 + ni * 8 + g) * CLD + k8 + tg;
                bh0 = Bh[bb]; bh1 = Bh[bb + 4];
                bl0 = Bl[bb]; bl1 = Bl[bb + 4];
            }
            mma_tf32(acc[ni], ah, bh0, bh1);
            mma_tf32(acc[ni], ah, bl0, bl1);
            mma_tf32(acc[ni], al, bh0, bh1);
        }
    }
}

// fragment (row, col) helpers: e0=(g,2tg) e1=(g,2tg+1) e2=(g+8,2tg) e3=(g+8,2tg+1)
#define FRAG_ROW(e) (m0 + g + ((e) >> 1 ? 8 : 0))
#define FRAG_COL(ni, e) (n0 + (ni) * 8 + 2 * tg + ((e) & 1))

// ---------------- K4: per-chunk MLP gradients (tensor cores) ----------------
#define CG_SMEM (9 * BUF * 4)
__global__ __launch_bounds__(256) void chunk_grad_tc(const float* __restrict__ w1,
                                                     const float* __restrict__ w2) {
    int id = blockIdx.x;               // bh*N_ + nn
    int bh = id >> 7, nn = id & 127;
    int b = bh >> 3, h = bh & 7;
    size_t tb = (size_t)b * T_ + (size_t)nn * C_;
    extern __shared__ uint32_t smu[];
    uint32_t* KCh = smu;
    uint32_t* KCl = smu + BUF;
    uint32_t* HHh = smu + 2 * BUF;     // holds W1 first, then HH, then DX1
    uint32_t* HHl = smu + 3 * BUF;
    uint32_t* W2h = smu + 4 * BUF;
    uint32_t* W2l = smu + 5 * BUF;
    float*    X1  = (float*)(smu + 6 * BUF);
    uint32_t* G2h = smu + 7 * BUF;
    uint32_t* G2l = smu + 8 * BUF;
    __shared__ float lrs[64];
    int tid = threadIdx.x;
    if (tid < 64) lrs[tid] = g_lr[(tb + tid) * H_ + h];
    for (int idx = tid; idx < 4096; idx += 256) {
        int i = idx >> 6, j = idx & 63;
        float kc = g_kv[(tb + i) * (2 * DIM_) + h * 64 + j];
        uint32_t hi = f2tf(kc);
        KCh[i * CLD + j] = hi; KCl[i * CLD + j] = f2tf(kc - __uint_as_float(hi));
        float a1 = w1[idx];
        hi = f2tf(a1);
        HHh[i * CLD + j] = hi; HHl[i * CLD + j] = f2tf(a1 - __uint_as_float(hi));
        float a2 = w2[idx];
        hi = f2tf(a2);
        W2h[i * CLD + j] = hi; W2l[i * CLD + j] = f2tf(a2 - __uint_as_float(hi));
    }
    __syncthreads();
    int lane = tid & 31, warp = tid >> 5;
    int m0 = (warp >> 1) * 16, n0 = (warp & 1) * 32;
    int g = lane >> 2, tg = lane & 3;
    float acc[4][4];

    // MM1: X1 = KC @ W1 ; HH = silu(X1)
    mm64_tc<false, false>(KCh, KCl, HHh, HHl, acc, m0, n0, g, tg);
    __syncthreads();   // all warps done reading W1 before overwrite
#pragma unroll
    for (int ni = 0; ni < 4; ni++)
#pragma unroll
        for (int e = 0; e < 4; e++) {
            int row = FRAG_ROW(e), col = FRAG_COL(ni, e);
            float x = acc[ni][e];
            X1[row * CLD + col] = x;
            float hv = x * sigmoidf_(x);
            uint32_t hi = f2tf(hv);
            HHh[row * CLD + col] = hi;
            HHl[row * CLD + col] = f2tf(hv - __uint_as_float(hi));
        }
    __syncthreads();

    // MM2: X2 = HH @ W2 ; G2 = (2 lr / 64)(X2 - v)
    mm64_tc<false, false>(HHh, HHl, W2h, W2l, acc, m0, n0, g, tg);
#pragma unroll
    for (int ni = 0; ni < 4; ni++)
#pragma unroll
        for (int e = 0; e < 4; e++) {
            int row = FRAG_ROW(e), col = FRAG_COL(ni, e);
            float vc = g_kv[(tb + row) * (2 * DIM_) + DIM_ + h * 64 + col];
            float gg = (2.f / 64.f) * lrs[row] * (acc[ni][e] - vc);
            uint32_t hi = f2tf(gg);
            G2h[row * CLD + col] = hi;
            G2l[row * CLD + col] = f2tf(gg - __uint_as_float(hi));
        }
    __syncthreads();

    // MM3: g2 = HH^T @ G2  -> store -g2
    mm64_tc<true, false>(HHh, HHl, G2h, G2l, acc, m0, n0, g, tg);
    size_t gbase = (size_t)id * 4096;
#pragma unroll
    for (int ni = 0; ni < 4; ni++) {
        int col = n0 + ni * 8 + 2 * tg;
        float2 v0 = {-acc[ni][0], -acc[ni][1]};
        float2 v1 = {-acc[ni][2], -acc[ni][3]};
        *(float2*)(g_g2 + gbase + (m0 + g) * 64 + col) = v0;
        *(float2*)(g_g2 + gbase + (m0 + 8 + g) * 64 + col) = v1;
    }
    __syncthreads();   // HH reads done before DX1 overwrite

    // MM4: DX1 = (G2 @ W2^T) * silu'(X1)  -> into HH bufs
    mm64_tc<false, true>(G2h, G2l, W2h, W2l, acc, m0, n0, g, tg);
#pragma unroll
    for (int ni = 0; ni < 4; ni++)
#pragma unroll
        for (int e = 0; e < 4; e++) {
            int row = FRAG_ROW(e), col = FRAG_COL(ni, e);
            float x = X1[row * CLD + col];
            float sg = sigmoidf_(x);
            float dv = acc[ni][e] * sg * (1.f + x * (1.f - sg));
            uint32_t hi = f2tf(dv);
            HHh[row * CLD + col] = hi;
            HHl[row * CLD + col] = f2tf(dv - __uint_as_float(hi));
        }
    __syncthreads();

    // MM5: g1 = KC^T @ DX1 -> store -g1
    mm64_tc<true, false>(KCh, KCl, HHh, HHl, acc, m0, n0, g, tg);
#pragma unroll
    for (int ni = 0; ni < 4; ni++) {
        int col = n0 + ni * 8 + 2 * tg;
        float2 v0 = {-acc[ni][0], -acc[ni][1]};
        float2 v1 = {-acc[ni][2], -acc[ni][3]};
        *(float2*)(g_g1 + gbase + (m0 + g) * 64 + col) = v0;
        *(float2*)(g_g1 + gbase + (m0 + 8 + g) * 64 + col) = v1;
    }
}

// ---------------- K5: double assoc-scan over n=128 chunks ----------------
__global__ __launch_bounds__(256) void scan_kernel(const float* __restrict__ w1,
                                                   const float* __restrict__ w2) {
    int bh = blockIdx.y;
    int idx = blockIdx.x * 256 + threadIdx.x;
    int b = bh >> 3, h = bh & 7;
    float w1v = w1[idx], w2v = w2[idx];
    float m1 = 0.f, u1 = 0.f, m2 = 0.f, u2 = 0.f;
    size_t base = ((size_t)bh * N_) * 4096 + idx;
    for (int nn = 0; nn < N_; nn++) {
        float mg = g_mom[((size_t)b * N_ + nn) * H_ + h];
        float dc = g_dec[((size_t)b * N_ + nn) * H_ + h];
        size_t off = base + (size_t)nn * 4096;
        float s1 = g_g1[off], s2 = g_g2[off];
        m1 = mg * m1 + s1; u1 = (1.f - dc) * u1 + m1; g_g1[off] = w1v + u1;
        m2 = mg * m2 + s2; u2 = (1.f - dc) * u2 + m2; g_g2[off] = w2v + u2;
    }
}

// ---------------- zero first 63 rows of vals (hi/lo) per batch ----------------
__global__ void zero_pad_kernel() {
    int idx = blockIdx.x * 256 + threadIdx.x;
    const int per = 63 * DIM_;
    if (idx < B_ * per) {
        int b = idx / per, r = idx % per;
        g_vh[(size_t)b * T_ * DIM_ + r] = 0u;
        g_vl[(size_t)b * T_ * DIM_ + r] = 0u;
    }
}

// ---------------- K6: retrieve (tensor cores) ----------------
#define RT_SMEM (6 * BUF * 4)
__global__ __launch_bounds__(256) void retrieve_tc(const float* __restrict__ gamma) {
    int id = blockIdx.x;
    int bh = id >> 7, nn = id & 127;
    int b = bh >> 3, h = bh & 7;
    extern __shared__ uint32_t smu[];
    uint32_t* Qh  = smu;
    uint32_t* Ql  = smu + BUF;
    uint32_t* HHh = smu + 2 * BUF;   // W1eff first, then HH
    uint32_t* HHl = smu + 3 * BUF;
    uint32_t* W2h = smu + 4 * BUF;
    uint32_t* W2l = smu + 5 * BUF;
    __shared__ float rowp[64][2];
    __shared__ float gam[64];
    __shared__ float rscale[64];
    int tid = threadIdx.x;
    int j0 = nn * C_;
    size_t gbase = (size_t)id * 4096;
    if (tid < 64) gam[tid] = gamma[h * 64 + tid] + 1.f;
    for (int idx = tid; idx < 4096; idx += 256) {
        int ci = idx >> 6, a = idx & 63;
        int i = j0 + ci + 63;
        float qv = (i < T_) ? g_q[((size_t)b * T_ + i) * DIM_ + h * 64 + a] : 0.f;
        uint32_t hi = f2tf(qv);
        Qh[ci * CLD + a] = hi; Ql[ci * CLD + a] = f2tf(qv - __uint_as_float(hi));
        float e1 = g_g1[gbase + idx];
        hi = f2tf(e1);
        HHh[ci * CLD + a] = hi; HHl[ci * CLD + a] = f2tf(e1 - __uint_as_float(hi));
        float e2 = g_g2[gbase + idx];
        hi = f2tf(e2);
        W2h[ci * CLD + a] = hi; W2l[ci * CLD + a] = f2tf(e2 - __uint_as_float(hi));
    }
    __syncthreads();
    int lane = tid & 31, warp = tid >> 5;
    int m0 = (warp >> 1) * 16, n0 = (warp & 1) * 32;
    int g = lane >> 2, tg = lane & 3;
    float acc[4][4];

    // MM1: X1 = Q @ W1eff ; HH = silu(X1)
    mm64_tc<false, false>(Qh, Ql, HHh, HHl, acc, m0, n0, g, tg);
    __syncthreads();
#pragma unroll
    for (int ni = 0; ni < 4; ni++)
#pragma unroll
        for (int e = 0; e < 4; e++) {
            int row = FRAG_ROW(e), col = FRAG_COL(ni, e);
            float x = acc[ni][e];
            float hv = x * sigmoidf_(x);
            uint32_t hi = f2tf(hv);
            HHh[row * CLD + col] = hi;
            HHl[row * CLD + col] = f2tf(hv - __uint_as_float(hi));
        }
    __syncthreads();

    // MM2: Y = HH @ W2eff (stays in acc)
    mm64_tc<false, false>(HHh, HHl, W2h, W2l, acc, m0, n0, g, tg);

    // per-row sum of squares via shfl over tg lanes
    float ss0 = 0.f, ss1 = 0.f;
#pragma unroll
    for (int ni = 0; ni < 4; ni++) {
        ss0 += acc[ni][0] * acc[ni][0] + acc[ni][1] * acc[ni][1];
        ss1 += acc[ni][2] * acc[ni][2] + acc[ni][3] * acc[ni][3];
    }
#pragma unroll
    for (int o = 1; o < 4; o <<= 1) {
        ss0 += __shfl_xor_sync(0xffffffffu, ss0, o);
        ss1 += __shfl_xor_sync(0xffffffffu, ss1, o);
    }
    if (tg == 0) {
        rowp[m0 + g][warp & 1] = ss0;
        rowp[m0 + 8 + g][warp & 1] = ss1;
    }
    __syncthreads();
    if (tid < 64) {
        int i = j0 + tid + 63;
        float gate = (i < T_) ? g_gate[((size_t)b * T_ + i) * H_ + h] : 0.f;
        float tot = rowp[tid][0] + rowp[tid][1];
        rscale[tid] = rsqrtf(tot * (1.f / 64.f) + EPSV) * gate;
    }
    __syncthreads();

    // scale + gamma, emit tf32 hi/lo vals
#pragma unroll
    for (int ni = 0; ni < 4; ni++)
#pragma unroll
        for (int e = 0; e < 4; e++) {
            int row = FRAG_ROW(e), col = FRAG_COL(ni, e);
            int i = j0 + row + 63;
            if (i < T_) {
                float v = acc[ni][e] * rscale[row] * gam[col];
                size_t oidx = ((size_t)b * T_ + i) * DIM_ + h * 64 + col;
                uint32_t hi = f2tf(v);
                g_vh[oidx] = hi;
                g_vl[oidx] = f2tf(v - __uint_as_float(hi));
            }
        }
}

// ---------------- launch ----------------
extern "C" void kernel_launch(void* const* d_in, const int* in_sizes, int n_in,
                              void* d_out, int out_size) {
    const float* seq      = (const float*)d_in[0];
    const float* w1       = (const float*)d_in[1];
    const float* w2       = (const float*)d_in[2];
    const float* Wq       = (const float*)d_in[3];
    const float* Wkv      = (const float*)d_in[4];
    const float* Wstep    = (const float*)d_in[5];
    const float* Wmom     = (const float*)d_in[6];
    const float* Wdecay   = (const float*)d_in[7];
    const float* Wgate    = (const float*)d_in[8];
    const float* Wcombine = (const float*)d_in[9];
    const float* gamma    = (const float*)d_in[10];
    float* out = (float*)d_out;
    (void)in_sizes; (void)n_in; (void)out_size;

    cudaFuncSetAttribute(gemm_tc, cudaFuncAttributeMaxDynamicSharedMemorySize, GEMM_SMEM);
    cudaFuncSetAttribute(chunk_grad_tc, cudaFuncAttributeMaxDynamicSharedMemorySize, CG_SMEM);
    cudaFuncSetAttribute(retrieve_tc, cudaFuncAttributeMaxDynamicSharedMemorySize, RT_SMEM);

    uint32_t *p_sh, *p_sl, *p_vh, *p_vl;
    uint32_t *p_wkvh, *p_wkvl, *p_wqh, *p_wql, *p_wch, *p_wcl;
    float *p_kv, *p_q;
    cudaGetSymbolAddress((void**)&p_sh, g_sh);
    cudaGetSymbolAddress((void**)&p_sl, g_sl);
    cudaGetSymbolAddress((void**)&p_vh, g_vh);
    cudaGetSymbolAddress((void**)&p_vl, g_vl);
    cudaGetSymbolAddress((void**)&p_wkvh, g_wkvh);
    cudaGetSymbolAddress((void**)&p_wkvl, g_wkvl);
    cudaGetSymbolAddress((void**)&p_wqh, g_wqh);
    cudaGetSymbolAddress((void**)&p_wql, g_wql);
    cudaGetSymbolAddress((void**)&p_wch, g_wch);
    cudaGetSymbolAddress((void**)&p_wcl, g_wcl);
    cudaGetSymbolAddress((void**)&p_kv, g_kv);
    cudaGetSymbolAddress((void**)&p_q, g_q);

    rmsnorm_kernel<<<B_ * T_, 256>>>(seq);
    cvt_kernel<<<(DIM_ * 2 * DIM_ + 255) / 256, 256>>>(Wkv, p_wkvh, p_wkvl, DIM_ * 2 * DIM_);
    cvt_kernel<<<(DIM_ * DIM_ + 255) / 256, 256>>>(Wq, p_wqh, p_wql, DIM_ * DIM_);
    cvt_kernel<<<(DIM_ * DIM_ + 255) / 256, 256>>>(Wcombine, p_wch, p_wcl, DIM_ * DIM_);
    proj_kernel<<<B_ * N_, 256>>>(Wstep, Wgate, Wmom, Wdecay);
    gemm_tc<<<dim3(2 * DIM_ / 128, B_ * T_ / 128), 256, GEMM_SMEM>>>(
        p_sh, p_sl, p_wkvh, p_wkvl, p_kv, B_ * T_, 2 * DIM_, DIM_);
    gemm_tc<<<dim3(DIM_ / 128, B_ * T_ / 128), 256, GEMM_SMEM>>>(
        p_sh, p_sl, p_wqh, p_wql, p_q, B_ * T_, DIM_, DIM_);
    chunk_grad_tc<<<BH_ * N_, 256, CG_SMEM>>>(w1, w2);
    scan_kernel<<<dim3(16, BH_), 256>>>(w1, w2);
    zero_pad_kernel<<<(B_ * 63 * DIM_ + 255) / 256, 256>>>();
    retrieve_tc<<<BH_ * N_, 256, RT_SMEM>>>(gamma);
    gemm_tc<<<dim3(DIM_ / 128, B_ * T_ / 128), 256, GEMM_SMEM>>>(
        p_vh, p_vl, p_wch, p_wcl, out, B_ * T_, DIM_, DIM_);
}